// round 9
// baseline (speedup 1.0000x reference)
#include <cuda_runtime.h>
#include <cuda_bf16.h>

// Causal convolution via FFT (Bailey four-step, N = 131072 = 256 x 512).
// Forward: DIF (natural in -> bit-reversed out), Inverse: DIT (bit-reversed in
// -> natural out) => no reordering anywhere; pointwise product done on
// identically-scrambled spectra.
//
//   n = n1*512 + n2   (n1 in [0,256), n2 in [0,512))
//   k = k2*256 + k1
//   F1:  length-256 DFT over n1 (columns, stride 512), then * W_N^{n2*k1}
//   F2:  length-512 DFT over n2 (rows, contiguous)
//   (fused) multiply + inverse rows + conj twiddle          [fmid_kernel]
//   I2:  inverse length-256 DFT over n1, scale 1/N, emit real part n < T
//
// Row index r after F1 holds k1 = bitrev8(r); row position q after F2 holds
// k2 = bitrev9(q). DIT inverses consume exactly those orders.

#define SEQ   512
#define T_LEN 65536
#define NFFT  131072
#define N1    256
#define N2    512

// 512 MiB each — static device scratch (allocation APIs are forbidden).
__device__ float2 g_bufx[(size_t)SEQ * NFFT];
__device__ float2 g_bufh[(size_t)SEQ * NFFT];
__device__ float2 g_tw[NFFT];   // W_N^k = exp(-2*pi*i*k/N)

__device__ __forceinline__ float2 cmul(float2 a, float2 b) {
    return make_float2(a.x * b.x - a.y * b.y, a.x * b.y + a.y * b.x);
}
__device__ __forceinline__ float2 cmulc(float2 a, float2 b) {  // a * conj(b)
    return make_float2(a.x * b.x + a.y * b.y, a.y * b.x - a.x * b.y);
}

__global__ void init_tw_kernel() {
    int i = blockIdx.x * blockDim.x + threadIdx.x;
    if (i < NFFT) {
        double ang = -6.283185307179586476925286766559 * (double)i / (double)NFFT;
        g_tw[i] = make_float2((float)cos(ang), (float)sin(ang));
    }
}

// ---------------------------------------------------------------------------
// Pass F1: column FFTs (length 256, stride 512). Tile: 256 rows x 16 cols.
// blockIdx = (col_tile [0,32), seq [0,512), which {0=x (bf16-quantized), 1=h})
// ---------------------------------------------------------------------------
__global__ __launch_bounds__(256) void f1_kernel(const float* __restrict__ x,
                                                 const float* __restrict__ h) {
    __shared__ float2 S[N1 * 16];    // 32 KiB
    __shared__ float2 w512[256];     // W_512^j

    const int t  = threadIdx.x;
    const int c  = t & 15;
    const int j  = t >> 4;
    const int c0 = blockIdx.x * 16;
    const int s  = blockIdx.y;
    const int which = blockIdx.z;

    w512[t] = g_tw[t << 8];

    const float* __restrict__ in  = (which ? h : x) + (size_t)s * T_LEN;
    float2*      __restrict__ out = (which ? g_bufh : g_bufx) + (size_t)s * NFFT;

    // Load padded signal: n = n1*512 + n2, nonzero only for n1 < 128.
    #pragma unroll
    for (int n1 = j; n1 < 128; n1 += 16) {
        float v = in[(n1 << 9) + c0 + c];
        if (which == 0) v = __bfloat162float(__float2bfloat16(v));  // bf16 quantize
        S[(n1 << 4) + c] = make_float2(v, 0.0f);
    }
    #pragma unroll
    for (int n1 = 128 + j; n1 < 256; n1 += 16)
        S[(n1 << 4) + c] = make_float2(0.0f, 0.0f);
    __syncthreads();

    // DIF radix-2, length 256.  Twiddle W_{2h}^{pos} = w512[pos << (8 - lh)].
    for (int lh = 7; lh >= 0; --lh) {
        const int hh = 1 << lh;
        #pragma unroll
        for (int i = 0; i < 8; ++i) {
            int b   = j + (i << 4);                  // butterfly index [0,128)
            int pos = b & (hh - 1);
            int g   = b >> lh;
            int i0  = (((g << (lh + 1)) + pos) << 4) + c;
            int i1  = i0 + (hh << 4);
            float2 a = S[i0], bb = S[i1];
            S[i0] = make_float2(a.x + bb.x, a.y + bb.y);
            float2 d = make_float2(a.x - bb.x, a.y - bb.y);
            S[i1] = cmul(d, w512[pos << (8 - lh)]);
        }
        __syncthreads();
    }

    // Store with interpass twiddle W_N^{k1 * n2}, k1 = bitrev8(r).
    const int n2 = c0 + c;
    #pragma unroll
    for (int r = j; r < 256; r += 16) {
        int k1 = (int)(__brev((unsigned)r) >> 24);
        float2 v = cmul(S[(r << 4) + c], g_tw[k1 * n2]);
        out[(r << 9) + n2] = v;
    }
}

// ---------------------------------------------------------------------------
// Fused middle pass: forward row FFTs (len 512) of X and H, pointwise product,
// inverse row FFT (DIT), conjugate interpass twiddle, store to g_bufx.
// Tile: 4 rows of X (smem rows 0-3) + 4 rows of H (smem rows 4-7).
// blockIdx = (row_tile [0,64), seq [0,512))
// ---------------------------------------------------------------------------
__global__ __launch_bounds__(256) void fmid_kernel() {
    __shared__ float2 S[8 * N2];     // 32 KiB: rows 0..3 = x, rows 4..7 = h
    __shared__ float2 w512[256];

    const int t  = threadIdx.x;
    const int r0 = blockIdx.x * 4;
    const int s  = blockIdx.y;

    w512[t] = g_tw[t << 8];

    const float2* __restrict__ bx = g_bufx + (size_t)s * NFFT;
    const float2* __restrict__ bh = g_bufh + (size_t)s * NFFT;

    #pragma unroll
    for (int i = 0; i < 8; ++i) {
        int idx = t + (i << 8);              // [0,2048)
        int rr  = idx >> 9;
        int p   = idx & 511;
        size_t ga = (size_t)((r0 + rr) << 9) + p;
        S[idx]        = bx[ga];
        S[idx + 2048] = bh[ga];
    }
    __syncthreads();

    // Forward DIF length-512 on all 8 rows (x and h together).
    for (int lh = 8; lh >= 0; --lh) {
        const int hh = 1 << lh;
        #pragma unroll
        for (int i = 0; i < 8; ++i) {
            int m   = t + (i << 8);          // [0,2048): 8 rows * 256 bflies
            int rr  = m >> 8;
            int b   = m & 255;
            int pos = b & (hh - 1);
            int g   = b >> lh;
            int p0  = (rr << 9) + (g << (lh + 1)) + pos;
            int p1  = p0 + hh;
            float2 a = S[p0], bb = S[p1];
            S[p0] = make_float2(a.x + bb.x, a.y + bb.y);
            float2 d = make_float2(a.x - bb.x, a.y - bb.y);
            S[p1] = cmul(d, w512[pos << (8 - lh)]);
        }
        __syncthreads();
    }

    // Pointwise product (both spectra identically bit-reversed along rows).
    #pragma unroll
    for (int i = 0; i < 8; ++i) {
        int idx = t + (i << 8);
        S[idx] = cmul(S[idx], S[idx + 2048]);
    }
    __syncthreads();

    // Inverse DIT length-512 on rows 0..3 (bit-reversed in -> natural out).
    for (int lh = 0; lh <= 8; ++lh) {
        const int hh = 1 << lh;
        #pragma unroll
        for (int i = 0; i < 4; ++i) {
            int m   = t + (i << 8);          // [0,1024): 4 rows * 256 bflies
            int rr  = m >> 8;
            int b   = m & 255;
            int pos = b & (hh - 1);
            int g   = b >> lh;
            int p0  = (rr << 9) + (g << (lh + 1)) + pos;
            int p1  = p0 + hh;
            float2 a   = S[p0];
            float2 tmp = cmulc(S[p1], w512[pos << (8 - lh)]);
            S[p0] = make_float2(a.x + tmp.x, a.y + tmp.y);
            S[p1] = make_float2(a.x - tmp.x, a.y - tmp.y);
        }
        __syncthreads();
    }

    // Store with conj interpass twiddle W_N^{-n2*k1}, k1 = bitrev8(row).
    float2* __restrict__ ob = g_bufx + (size_t)s * NFFT;
    #pragma unroll
    for (int i = 0; i < 8; ++i) {
        int idx = t + (i << 8);              // [0,2048)
        int rr  = idx >> 9;
        int p   = idx & 511;                 // natural n2
        int k1  = (int)(__brev((unsigned)(r0 + rr)) >> 24);
        float2 v = cmulc(S[idx], g_tw[k1 * p]);
        ob[(size_t)((r0 + rr) << 9) + p] = v;
    }
}

// ---------------------------------------------------------------------------
// Pass I2: inverse column FFTs (length 256, DIT), scale 1/N, write real part
// for n = n1*512 + n2 < T (i.e. n1 < 128).  Tile: 256 rows x 16 cols.
// blockIdx = (col_tile [0,32), seq [0,512))
// ---------------------------------------------------------------------------
__global__ __launch_bounds__(256) void i2_kernel(float* __restrict__ out) {
    __shared__ float2 S[N1 * 16];
    __shared__ float2 w512[256];

    const int t  = threadIdx.x;
    const int c  = t & 15;
    const int j  = t >> 4;
    const int c0 = blockIdx.x * 16;
    const int s  = blockIdx.y;

    w512[t] = g_tw[t << 8];

    const float2* __restrict__ ib = g_bufx + (size_t)s * NFFT;
    #pragma unroll
    for (int r = j; r < 256; r += 16)
        S[(r << 4) + c] = ib[(r << 9) + c0 + c];
    __syncthreads();

    // Inverse DIT length-256 (bit-reversed in -> natural n1 out).
    for (int lh = 0; lh <= 7; ++lh) {
        const int hh = 1 << lh;
        #pragma unroll
        for (int i = 0; i < 8; ++i) {
            int b   = j + (i << 4);          // [0,128)
            int pos = b & (hh - 1);
            int g   = b >> lh;
            int i0  = (((g << (lh + 1)) + pos) << 4) + c;
            int i1  = i0 + (hh << 4);
            float2 a   = S[i0];
            float2 tmp = cmulc(S[i1], w512[pos << (8 - lh)]);
            S[i0] = make_float2(a.x + tmp.x, a.y + tmp.y);
            S[i1] = make_float2(a.x - tmp.x, a.y - tmp.y);
        }
        __syncthreads();
    }

    float* __restrict__ ob = out + (size_t)s * T_LEN;
    const float scale = 1.0f / (float)NFFT;
    #pragma unroll
    for (int n1 = j; n1 < 128; n1 += 16)
        ob[(n1 << 9) + c0 + c] = S[(n1 << 4) + c].x * scale;
}

extern "C" void kernel_launch(void* const* d_in, const int* in_sizes, int n_in,
                              void* d_out, int out_size) {
    (void)in_sizes; (void)n_in; (void)out_size;
    const float* x = (const float*)d_in[0];
    const float* h = (const float*)d_in[1];
    float* out = (float*)d_out;

    init_tw_kernel<<<NFFT / 256, 256>>>();
    f1_kernel<<<dim3(32, SEQ, 2), 256>>>(x, h);
    fmid_kernel<<<dim3(64, SEQ), 256>>>();
    i2_kernel<<<dim3(32, SEQ), 256>>>(out);
}

// round 11
// speedup vs baseline: 2.0566x; 2.0566x over previous
#include <cuda_runtime.h>
#include <cuda_bf16.h>

// Causal convolution via FFT (Bailey four-step, N = 131072 = 256 x 512),
// all sub-FFTs natural-order register four-step:
//   256 = 16x16  (two in-register 16-pt FFTs + one smem transpose)
//   512 = 16x32  (16-pt FFTs + pair-split 32-pt DFT via shfl_xor)
// No bit reversal anywhere; every pass produces/consumes natural order.
//
//   n = n1*512 + n2 ;  k = k2*256 + k1
//   F1 : 256-pt DFT over n1 (cols), * W_N^{k1*n2}          -> rows = k1 natural
//   FM : fwd 512-pt rows of X,H; pointwise product; inv 512-pt rows; *W_N^{-k1*n2}
//   I2 : inverse 256-pt over k1, scale 1/N, emit real part (n1 < 128)

#define SEQ   512
#define T_LEN 65536
#define NFFT  131072

__device__ float2 g_bufx[(size_t)SEQ * NFFT];
__device__ float2 g_bufh[(size_t)SEQ * NFFT];
__device__ float2 g_tw[NFFT];   // W_N^k = exp(-2*pi*i*k/N)

__device__ __forceinline__ float2 cmul(float2 a, float2 b) {
    return make_float2(a.x * b.x - a.y * b.y, a.x * b.y + a.y * b.x);
}
__device__ __forceinline__ float2 cmulc(float2 a, float2 b) {  // a * conj(b)
    return make_float2(a.x * b.x + a.y * b.y, a.y * b.x - a.x * b.y);
}

__global__ void init_tw_kernel() {
    int i = blockIdx.x * blockDim.x + threadIdx.x;
    if (i < NFFT) {
        double ang = -6.283185307179586476925286766559 * (double)i / (double)NFFT;
        g_tw[i] = make_float2((float)cos(ang), (float)sin(ang));
    }
}

// ---------------------------------------------------------------------------
// In-register 16-point FFT, natural in -> natural out. INV = conjugate kernel.
// ---------------------------------------------------------------------------
template<bool INV>
__device__ __forceinline__ void r4(float2 x0, float2 x1, float2 x2, float2 x3,
                                   float2& y0, float2& y1, float2& y2, float2& y3) {
    float2 s0 = make_float2(x0.x + x2.x, x0.y + x2.y);
    float2 d0 = make_float2(x0.x - x2.x, x0.y - x2.y);
    float2 s1 = make_float2(x1.x + x3.x, x1.y + x3.y);
    float2 d1 = make_float2(x1.x - x3.x, x1.y - x3.y);
    y0 = make_float2(s0.x + s1.x, s0.y + s1.y);
    y2 = make_float2(s0.x - s1.x, s0.y - s1.y);
    if (!INV) {
        y1 = make_float2(d0.x + d1.y, d0.y - d1.x);   // d0 - i d1
        y3 = make_float2(d0.x - d1.y, d0.y + d1.x);   // d0 + i d1
    } else {
        y1 = make_float2(d0.x - d1.y, d0.y + d1.x);
        y3 = make_float2(d0.x + d1.y, d0.y - d1.x);
    }
}

template<bool INV>
__device__ __forceinline__ float2 w16mul(float2 v, int e) {
    const float C1 = 0.9238795325112867f;
    const float S1 = 0.3826834323650898f;
    const float R2 = 0.7071067811865476f;
    float2 w;
    switch (e) {
        case 0: return v;
        case 1: w = make_float2( C1, -S1); break;
        case 2: w = make_float2( R2, -R2); break;
        case 3: w = make_float2( S1, -C1); break;
        case 4: return INV ? make_float2(-v.y, v.x) : make_float2(v.y, -v.x);
        case 6: w = make_float2(-R2, -R2); break;
        case 9: w = make_float2(-C1,  S1); break;
        default: w = make_float2(1.f, 0.f); break;
    }
    return INV ? cmulc(v, w) : cmul(v, w);
}

template<bool INV>
__device__ __forceinline__ void fft16(float2 v[16]) {
    float2 w[16];
    #pragma unroll
    for (int a0 = 0; a0 < 4; ++a0) {
        float2 y0, y1, y2, y3;
        r4<INV>(v[a0], v[a0 + 4], v[a0 + 8], v[a0 + 12], y0, y1, y2, y3);
        w[a0]      = y0;
        w[4 + a0]  = w16mul<INV>(y1, a0);
        w[8 + a0]  = w16mul<INV>(y2, 2 * a0);
        w[12 + a0] = w16mul<INV>(y3, 3 * a0);
    }
    #pragma unroll
    for (int k0 = 0; k0 < 4; ++k0) {
        float2 y0, y1, y2, y3;
        r4<INV>(w[4 * k0], w[4 * k0 + 1], w[4 * k0 + 2], w[4 * k0 + 3], y0, y1, y2, y3);
        v[k0]      = y0;                 // X[4*k1 + k0]
        v[4 + k0]  = y1;
        v[8 + k0]  = y2;
        v[12 + k0] = y3;
    }
}

// ---------------------------------------------------------------------------
// F1: length-256 column FFTs (stride 512), natural out, * W_N^{k1*n2}.
// Block: 256 thr = 16 cols x 16. Grid: (32, 512, 2). n1 = a*16 + b, k1 = d*16 + c.
// ---------------------------------------------------------------------------
__global__ __launch_bounds__(256) void f1_kernel(const float* __restrict__ x,
                                                 const float* __restrict__ h) {
    __shared__ float2 S[4096];       // [c][b][col]
    __shared__ float2 w256s[256];    // W_256^i

    const int t = threadIdx.x, col = t & 15, idx = t >> 4;
    const int c0 = blockIdx.x * 16, s = blockIdx.y, which = blockIdx.z;
    const int n2 = c0 + col;

    w256s[t] = g_tw[t << 9];

    const float* __restrict__ in  = (which ? h : x) + (size_t)s * T_LEN;
    float2*      __restrict__ out = (which ? g_bufh : g_bufx) + (size_t)s * NFFT;

    float2 v[16];
    {   // phase 1: DFT over a, thread owns b = idx
        const int b = idx;
        #pragma unroll
        for (int a = 0; a < 8; ++a) {          // n1 = 16a + b < 128 nonzero
            float val = in[(((a << 4) + b) << 9) + n2];
            if (which == 0) val = __bfloat162float(__float2bfloat16(val));
            v[a] = make_float2(val, 0.f);
        }
        #pragma unroll
        for (int a = 8; a < 16; ++a) v[a] = make_float2(0.f, 0.f);
        fft16<false>(v);                        // -> Y[c]
        __syncthreads();                        // w256s ready
        #pragma unroll
        for (int c = 0; c < 16; ++c)
            S[c * 256 + b * 16 + col] = cmul(v[c], w256s[b * c]);
    }
    __syncthreads();
    {   // phase 2: DFT over b, thread owns c = idx
        const int c = idx;
        #pragma unroll
        for (int b = 0; b < 16; ++b) v[b] = S[c * 256 + b * 16 + col];
        fft16<false>(v);                        // -> X[16d + c]
        float2 cw = g_tw[c * n2];               // W_N^{c*n2}
        const float2 st = g_tw[n2 << 4];        // W_N^{16*n2}
        #pragma unroll
        for (int d = 0; d < 16; ++d) {
            out[(((d << 4) + c) << 9) + n2] = cmul(v[d], cw);
            cw = cmul(cw, st);
        }
    }
}

// ---------------------------------------------------------------------------
// FM: fused forward row FFTs (512 = 16x32), product, inverse rows, conj twiddle.
// Block: 256 thr = 8 rows (4 x + 4 h) x 32. Grid: (64, 512).
// n2 = a*32 + b ; spectral k2-position p = 16m + c (natural).
// ---------------------------------------------------------------------------
__global__ __launch_bounds__(256) void fmid_kernel() {
    __shared__ float2 S[8 * 512];
    __shared__ float2 w512s[512];    // W_512^i ; W_32^k = w512s[16k]

    const int t = threadIdx.x;
    const int r0 = blockIdx.x * 4, s = blockIdx.y;

    w512s[t]       = g_tw[t << 8];
    w512s[t + 256] = g_tw[(t + 256) << 8];

    const float2* __restrict__ bx = g_bufx + (size_t)s * NFFT;
    const float2* __restrict__ bh = g_bufh + (size_t)s * NFFT;

    float2 v[16];

    // ---- forward phase 1: 16-pt DFT over a, per (row8, b) ----
    {
        const int row8 = t >> 5, b = t & 31;
        const float2* __restrict__ src =
            (row8 < 4) ? bx + ((size_t)(r0 + row8) << 9)
                       : bh + ((size_t)(r0 + row8 - 4) << 9);
        #pragma unroll
        for (int a = 0; a < 16; ++a) v[a] = src[(a << 5) + b];
        fft16<false>(v);                        // -> Y[c]
        __syncthreads();                        // w512s ready
        #pragma unroll
        for (int c = 0; c < 16; ++c)
            S[(row8 << 9) + (c << 5) + b] = cmul(v[c], w512s[b * c]);
    }
    __syncthreads();

    // ---- forward phase 2: 32-pt DFT over b, pair-split by parity ----
    {
        const int row8 = t >> 5, tc = t & 31, c = tc >> 1, half = tc & 1;
        #pragma unroll
        for (int j = 0; j < 16; ++j) {          // rotated order: avoid 16-way conflicts
            int jj = (j + c) & 15;
            v[jj] = S[(row8 << 9) + (c << 5) + (jj << 1) + half];
        }
        __syncthreads();                        // all reads done before overwrite
        fft16<false>(v);                        // E[k] (half=0) or O[k] (half=1)
        if (half) {
            #pragma unroll
            for (int k = 0; k < 16; ++k) v[k] = cmul(v[k], w512s[k << 4]);  // *W32^k
        }
        #pragma unroll
        for (int k = 0; k < 16; ++k) {
            float2 o;
            o.x = __shfl_xor_sync(0xFFFFFFFFu, v[k].x, 1);
            o.y = __shfl_xor_sync(0xFFFFFFFFu, v[k].y, 1);
            float2 X = half ? make_float2(o.x - v[k].x, o.y - v[k].y)   // X[k+16]
                            : make_float2(v[k].x + o.x, v[k].y + o.y);  // X[k]
            int m = (half << 4) + k;
            S[(row8 << 9) + (m << 4) + c] = X;  // spectrum, natural p = 16m + c
        }
    }
    __syncthreads();

    // ---- product + inverse phase A: inv 32-pt DFT over m, rows 0-3 ----
    {
        const int row4 = t >> 5, tc = t & 31, c = tc >> 1, par = tc & 1;
        float2 p[16];
        if (t < 128) {
            #pragma unroll
            for (int j = 0; j < 16; ++j) {
                int m = (par << 4) + j;
                float2 xv = S[(row4 << 9) + (m << 4) + c];
                float2 hv = S[((row4 + 4) << 9) + (m << 4) + c];
                p[j] = cmul(xv, hv);
            }
        }
        __syncthreads();                        // reads done before overwrite
        if (t < 128) {
            #pragma unroll
            for (int j = 0; j < 16; ++j) {      // S_par[j] = P[j] + (-1)^par P[j+16]
                float2 o;
                o.x = __shfl_xor_sync(0xFFFFFFFFu, p[j].x, 1);
                o.y = __shfl_xor_sync(0xFFFFFFFFu, p[j].y, 1);
                p[j] = par ? make_float2(o.x - p[j].x, o.y - p[j].y)
                           : make_float2(p[j].x + o.x, p[j].y + o.y);
            }
            if (par) {
                #pragma unroll
                for (int j = 0; j < 16; ++j) p[j] = cmulc(p[j], w512s[j << 4]);
            }
            fft16<true>(p);                     // -> Z[2b' + par]
            #pragma unroll
            for (int j = 0; j < 16; ++j) {      // rotated store order
                int bb = (j + c) & 15;
                int b  = (bb << 1) + par;
                S[(row4 << 9) + (c << 5) + b] = cmulc(p[bb], w512s[b * c]);
            }
        }
    }
    __syncthreads();

    // ---- inverse phase B: inv 16-pt over c, conj interpass twiddle, store ----
    if (t < 128) {
        const int row4 = t >> 5, b = t & 31;
        #pragma unroll
        for (int c = 0; c < 16; ++c) v[c] = S[(row4 << 9) + (c << 5) + b];
        fft16<true>(v);                         // -> x[32a + b]
        const int k1 = r0 + row4;
        float2 cw = g_tw[k1 * b];
        const float2 st = g_tw[k1 << 5];        // W_N^{32*k1}
        float2* __restrict__ ob = g_bufx + (size_t)s * NFFT + ((size_t)k1 << 9);
        #pragma unroll
        for (int a = 0; a < 16; ++a) {
            ob[(a << 5) + b] = cmulc(v[a], cw); // * conj(W_N^{k1*n2})
            cw = cmul(cw, st);
        }
    }
}

// ---------------------------------------------------------------------------
// I2: inverse 256-pt over k1 (natural in/out), scale 1/N, real part, n1 < 128.
// Block: 256 thr = 16 cols x 16. Grid: (32, 512). k1 = 16d + c, n1 = 16a + b.
// ---------------------------------------------------------------------------
__global__ __launch_bounds__(256) void i2_kernel(float* __restrict__ outp) {
    __shared__ float2 S[4096];       // [b][c][col]
    __shared__ float2 w256s[256];

    const int t = threadIdx.x, col = t & 15, idx = t >> 4;
    const int c0 = blockIdx.x * 16, s = blockIdx.y;
    const int n2 = c0 + col;

    w256s[t] = g_tw[t << 9];

    const float2* __restrict__ ib = g_bufx + (size_t)s * NFFT;
    float2 v[16];
    {   // phase 1: inverse DFT over d, thread owns c = idx
        const int c = idx;
        #pragma unroll
        for (int d = 0; d < 16; ++d) v[d] = ib[(((d << 4) + c) << 9) + n2];
        fft16<true>(v);                         // -> Z[b]
        __syncthreads();                        // w256s ready
        #pragma unroll
        for (int b = 0; b < 16; ++b)
            S[b * 256 + c * 16 + col] = cmulc(v[b], w256s[b * c]);
    }
    __syncthreads();
    {   // phase 2: inverse DFT over c, thread owns b = idx
        const int b = idx;
        #pragma unroll
        for (int c = 0; c < 16; ++c) v[c] = S[b * 256 + c * 16 + col];
        fft16<true>(v);                         // -> x[16a + b]
        float* __restrict__ ob = outp + (size_t)s * T_LEN;
        const float sc = 1.0f / (float)NFFT;
        #pragma unroll
        for (int a = 0; a < 8; ++a)             // n1 = 16a + b < 128
            ob[(((a << 4) + b) << 9) + n2] = v[a].x * sc;
    }
}

extern "C" void kernel_launch(void* const* d_in, const int* in_sizes, int n_in,
                              void* d_out, int out_size) {
    (void)in_sizes; (void)n_in; (void)out_size;
    const float* x = (const float*)d_in[0];
    const float* h = (const float*)d_in[1];
    float* out = (float*)d_out;

    init_tw_kernel<<<NFFT / 256, 256>>>();
    f1_kernel<<<dim3(32, SEQ, 2), 256>>>(x, h);
    fmid_kernel<<<dim3(64, SEQ), 256>>>();
    i2_kernel<<<dim3(32, SEQ), 256>>>(out);
}